// round 14
// baseline (speedup 1.0000x reference)
#include <cuda_runtime.h>
#include <cuda_bf16.h>
#include <math.h>

#define KTOP 50
#define TT   40
#define VV   30000
#define VP   30080          // 235*128
#define THH  800
#define EHH  200
#define EE   300
#define EP   304            // padded E (multiple of 8, = 19*16)
#define LL   3
#define BB   100
#define MP   2048           // padded logits rows (16*128), real rows = 2000

#define EPSF   1e-6f
#define DELTAF 0.005f
#define LOGDF  -5.2983173665480363f

#define SMS32 156           // mma smem row stride in 32-bit words (= 312 bf16)

// LSTM persistent kernel config
#define NBLK 8
#define HSL  (EHH/NBLK)     // 25
#define LROWS (4*HSL)       // 100
#define LSTR 204

// tf32 theta GEMM config
#define TZ   75             // split-K factor
#define TKC  400            // kchunk (75*400 = 30000 exactly)
#define TSTR 20             // smem row stride (floats)

// ------------- static device scratch -------------
__device__ float  d_x[TT*EHH];
__device__ float  d_y[TT*EHH];
__device__ float  d_gin[TT*4*EHH];
__device__ float  d_eta[TT*KTOP];
__device__ __nv_bfloat16 d_alphab[MP*EP];
__device__ __nv_bfloat16 d_wembb[(size_t)VP*EP];
__device__ float  d_hth[BB*THH];
__device__ float  d_mu_t[BB*KTOP];
__device__ float  d_ls_t[BB*KTOP];
__device__ float  d_theta[BB*KTOP];
__device__ float  d_rowsum[MP];
__device__ double d_scald[4];
__device__ __nv_bfloat16 d_elogh[(size_t)MP*VP];
__device__ unsigned int d_syncv[LL];
__device__ float  d_hbuf2[2][EHH];

// ------------- helpers -------------
__device__ __forceinline__ float warp_sum(float v) {
#pragma unroll
    for (int o = 16; o; o >>= 1) v += __shfl_xor_sync(0xffffffffu, v, o);
    return v;
}
__device__ __forceinline__ float sigmf(float x) { return 1.f / (1.f + __expf(-x)); }
__device__ __forceinline__ unsigned int f2tf32(float v) {
    unsigned int u;
    asm("cvt.rna.tf32.f32 %0, %1;" : "=r"(u) : "f"(v));
    return u;
}

__device__ __forceinline__ void block_add_double(float v, int slot) {
    __shared__ float red[8];
    int lane = threadIdx.x & 31, wid = threadIdx.x >> 5;
    v = warp_sum(v);
    if (lane == 0) red[wid] = v;
    __syncthreads();
    if (threadIdx.x == 0) {
        float tot = 0.f;
        int nw = (blockDim.x + 31) >> 5;
        for (int w = 0; w < nw; w++) tot += red[w];
        atomicAdd(&d_scald[slot], (double)tot);
    }
}

// ------------- zero -------------
__global__ void k_zero() {
    int i = blockIdx.x * blockDim.x + threadIdx.x;
    if (i < BB*THH) d_hth[i] = 0.f;
    if (i < TT*EHH) d_x[i] = 0.f;
    if (i < MP)     d_rowsum[i] = 0.f;
    if (i < 4)      d_scald[i] = 0.0;
    if (i < LL)     d_syncv[i] = 0u;
}

// ------------- bf16 conversions -------------
__global__ void k_alphaT(const float* __restrict__ mq) {
    int idx = blockIdx.x * blockDim.x + threadIdx.x;
    if (idx >= MP*EP) return;
    int row = idx / EP, e = idx % EP;
    int t = row / KTOP, k = row % KTOP;
    float v = (row < TT*KTOP && e < EE) ? mq[(k*TT + t)*EE + e] : 0.f;
    d_alphab[idx] = __float2bfloat16_rn(v);
}
__global__ void k_wembpad(const float* __restrict__ we) {
    size_t idx = (size_t)blockIdx.x * blockDim.x + threadIdx.x;
    if (idx >= (size_t)VP*EP) return;
    int v = (int)(idx / EP), e = (int)(idx % EP);
    float x = (v < VV && e < EE) ? we[(size_t)v*EE + e] : 0.f;
    d_wembb[idx] = __float2bfloat16_rn(x);
}

// ------------- generic split-K SGEMM (W_map path) -------------
__global__ void __launch_bounds__(256) k_sgemm_atomic(
        const float* __restrict__ A, int lda,
        const float* __restrict__ B, int ldb,
        float* __restrict__ C, int M, int N, int kchunk) {
    __shared__ float As[8][64];
    __shared__ float Bs[8][64];
    const int k0b = blockIdx.z * kchunk;
    const int bm = blockIdx.y * 64, bn = blockIdx.x * 64;
    const int tid = threadIdx.x;
    const int lr = tid >> 2, lk = (tid & 3) * 2;
    const int tx = tid & 15, ty = tid >> 4;
    float acc[4][4];
#pragma unroll
    for (int i = 0; i < 4; i++)
#pragma unroll
        for (int j = 0; j < 4; j++) acc[i][j] = 0.f;

    const int kend = k0b + kchunk;
    for (int k0 = k0b; k0 < kend; k0 += 8) {
        float2 av = make_float2(0.f,0.f), bv = make_float2(0.f,0.f);
        int am = bm + lr, bn2 = bn + lr;
        if (am < M) av = *(const float2*)&A[(size_t)am*lda + k0 + lk];
        if (bn2 < N) bv = *(const float2*)&B[(size_t)bn2*ldb + k0 + lk];
        As[lk][lr] = av.x; As[lk+1][lr] = av.y;
        Bs[lk][lr] = bv.x; Bs[lk+1][lr] = bv.y;
        __syncthreads();
#pragma unroll
        for (int kk = 0; kk < 8; kk++) {
            float a[4], b[4];
            *(float4*)a = *(const float4*)&As[kk][ty*4];
            *(float4*)b = *(const float4*)&Bs[kk][tx*4];
#pragma unroll
            for (int i = 0; i < 4; i++)
#pragma unroll
                for (int j = 0; j < 4; j++) acc[i][j] += a[i]*b[j];
        }
        __syncthreads();
    }
#pragma unroll
    for (int i = 0; i < 4; i++) {
        int m = bm + ty*4 + i;
        if (m >= M) continue;
#pragma unroll
        for (int j = 0; j < 4; j++) {
            int n = bn + tx*4 + j;
            if (n < N) atomicAdd(&C[(size_t)m*N + n], acc[i][j]);
        }
    }
}

// ------------- tf32 MMA split-K GEMM (theta path) -------------
// C[m,n] += sum_k A[m,k]*B[n,k]; grid (7, 1, TZ), 256 threads = 8 warps (2x4),
// warp tile 64x32 (mma m16n8k8 tf32), k-slab 16 per iter, atomic accumulate.
// NOTE: B rows (ldb=30050) are only 8-byte aligned -> float2 loads for B.
__global__ void __launch_bounds__(256, 2) k_gemm_tf32(
        const float* __restrict__ A, int lda, int M,
        const float* __restrict__ B, int ldb, int N,
        float* __restrict__ C, int ldc) {
    __shared__ float sA[128*TSTR];
    __shared__ float sB[128*TSTR];
    const int tid = threadIdx.x;
    const int bn = blockIdx.x * 128;
    const int kk0 = (int)blockIdx.z * TKC;

    const int w = tid >> 5;
    const int wm = w & 1;           // 0..1 (M strip of 64)
    const int wn = w >> 1;          // 0..3 (N strip of 32)
    const int lane = tid & 31;
    const int g = lane >> 2;        // 0..7
    const int t = lane & 3;         // 0..3

    float c[4][4][4];
#pragma unroll
    for (int mt = 0; mt < 4; mt++)
#pragma unroll
        for (int nt = 0; nt < 4; nt++)
#pragma unroll
            for (int q = 0; q < 4; q++) c[mt][nt][q] = 0.f;

    const int lrow = tid >> 2;      // 0..63
    const int lq   = (tid & 3) * 4; // float4 offset in 16-float slab

    for (int it = 0; it < TKC/16; it++) {
        const int k0 = kk0 + it*16;
        // load A/B slabs: 128 rows x 16 floats each; 2 reps of 64 rows
#pragma unroll
        for (int rep = 0; rep < 2; rep++) {
            int row = lrow + rep*64;
            float4 av = make_float4(0.f,0.f,0.f,0.f);
            float4 bv = make_float4(0.f,0.f,0.f,0.f);
            if (row < M)      av = *(const float4*)&A[(size_t)row*lda + k0 + lq];
            if (bn + row < N) {
                const float* bp = &B[(size_t)(bn + row)*ldb + k0 + lq];
                float2 u = *(const float2*)bp;          // 8B-aligned safe
                float2 v2 = *(const float2*)(bp + 2);
                bv = make_float4(u.x, u.y, v2.x, v2.y);
            }
            *(float4*)&sA[row*TSTR + lq] = av;
            *(float4*)&sB[row*TSTR + lq] = bv;
        }
        __syncthreads();
#pragma unroll
        for (int ks = 0; ks < 16; ks += 8) {
            unsigned int af[4][4], bf[4][2];
#pragma unroll
            for (int mt = 0; mt < 4; mt++) {
                int base = (wm*64 + mt*16 + g)*TSTR + ks + t;
                af[mt][0] = f2tf32(sA[base]);
                af[mt][1] = f2tf32(sA[base + 8*TSTR]);
                af[mt][2] = f2tf32(sA[base + 4]);
                af[mt][3] = f2tf32(sA[base + 8*TSTR + 4]);
            }
#pragma unroll
            for (int nt = 0; nt < 4; nt++) {
                int base = (wn*32 + nt*8 + g)*TSTR + ks + t;
                bf[nt][0] = f2tf32(sB[base]);
                bf[nt][1] = f2tf32(sB[base + 4]);
            }
#pragma unroll
            for (int mt = 0; mt < 4; mt++)
#pragma unroll
                for (int nt = 0; nt < 4; nt++)
                    asm volatile(
                        "mma.sync.aligned.m16n8k8.row.col.f32.tf32.tf32.f32 "
                        "{%0,%1,%2,%3}, {%4,%5,%6,%7}, {%8,%9}, {%0,%1,%2,%3};"
                        : "+f"(c[mt][nt][0]), "+f"(c[mt][nt][1]),
                          "+f"(c[mt][nt][2]), "+f"(c[mt][nt][3])
                        : "r"(af[mt][0]), "r"(af[mt][1]), "r"(af[mt][2]), "r"(af[mt][3]),
                          "r"(bf[nt][0]), "r"(bf[nt][1]));
        }
        __syncthreads();
    }

#pragma unroll
    for (int mt = 0; mt < 4; mt++) {
        int m0 = wm*64 + mt*16 + g;
#pragma unroll
        for (int nt = 0; nt < 4; nt++) {
            int n0 = bn + wn*32 + nt*8 + 2*t;
            if (m0 < M) {
                if (n0   < N) atomicAdd(&C[(size_t)m0*ldc + n0],   c[mt][nt][0]);
                if (n0+1 < N) atomicAdd(&C[(size_t)m0*ldc + n0+1], c[mt][nt][1]);
            }
            if (m0 + 8 < M) {
                if (n0   < N) atomicAdd(&C[(size_t)(m0+8)*ldc + n0],   c[mt][nt][2]);
                if (n0+1 < N) atomicAdd(&C[(size_t)(m0+8)*ldc + n0+1], c[mt][nt][3]);
            }
        }
    }
}

// ------------- bf16 HMMA logits GEMM: 128x128 tile, exp->bf16 + rowsum -------------
__global__ void __launch_bounds__(256, 1) k_gemm_mma() {
    extern __shared__ unsigned int smw[];
    unsigned int* sA = smw;
    unsigned int* sB = smw + 128*SMS32;
    const int tid = threadIdx.x;
    const int bm = blockIdx.y * 128, bn = blockIdx.x * 128;

    {
        const uint4* gA = (const uint4*)(d_alphab + (size_t)bm*EP);
        const uint4* gB = (const uint4*)(d_wembb + (size_t)bn*EP);
        uint4* s4A = (uint4*)sA;
        uint4* s4B = (uint4*)sB;
        for (int i = tid; i < 128*38; i += 256) {
            int row = i / 38, c = i % 38;
            s4A[row*39 + c] = gA[row*38 + c];
            s4B[row*39 + c] = gB[row*38 + c];
        }
    }
    __syncthreads();

    const int w   = tid >> 5;
    const int wm  = w & 1;
    const int wn  = w >> 1;
    const int lane = tid & 31;
    const int g = lane >> 2;
    const int t = lane & 3;

    float c[4][4][4];
#pragma unroll
    for (int mt = 0; mt < 4; mt++)
#pragma unroll
        for (int nt = 0; nt < 4; nt++)
#pragma unroll
            for (int q = 0; q < 4; q++) c[mt][nt][q] = 0.f;

    const unsigned int* sAb = sA + (wm*64 + g)*SMS32 + t;
    const unsigned int* sBb = sB + (wn*32 + g)*SMS32 + t;

    for (int kk = 0; kk < EP/16; kk++) {
        const int ko = kk*8;
        unsigned int a[4][4], b[4][2];
#pragma unroll
        for (int mt = 0; mt < 4; mt++) {
            const unsigned int* p = sAb + mt*16*SMS32 + ko;
            a[mt][0] = p[0];
            a[mt][1] = p[8*SMS32];
            a[mt][2] = p[4];
            a[mt][3] = p[8*SMS32 + 4];
        }
#pragma unroll
        for (int nt = 0; nt < 4; nt++) {
            const unsigned int* p = sBb + nt*8*SMS32 + ko;
            b[nt][0] = p[0];
            b[nt][1] = p[4];
        }
#pragma unroll
        for (int mt = 0; mt < 4; mt++)
#pragma unroll
            for (int nt = 0; nt < 4; nt++)
                asm volatile(
                    "mma.sync.aligned.m16n8k16.row.col.f32.bf16.bf16.f32 "
                    "{%0,%1,%2,%3}, {%4,%5,%6,%7}, {%8,%9}, {%0,%1,%2,%3};"
                    : "+f"(c[mt][nt][0]), "+f"(c[mt][nt][1]),
                      "+f"(c[mt][nt][2]), "+f"(c[mt][nt][3])
                    : "r"(a[mt][0]), "r"(a[mt][1]), "r"(a[mt][2]), "r"(a[mt][3]),
                      "r"(b[nt][0]), "r"(b[nt][1]));
    }

#pragma unroll
    for (int mt = 0; mt < 4; mt++) {
        float rs0 = 0.f, rs1 = 0.f;
        int row0 = bm + wm*64 + mt*16 + g;
#pragma unroll
        for (int nt = 0; nt < 4; nt++) {
            int n = bn + wn*32 + nt*8 + t*2;
            float e0 = __expf(c[mt][nt][0]);
            float e1 = __expf(c[mt][nt][1]);
            float e2 = __expf(c[mt][nt][2]);
            float e3 = __expf(c[mt][nt][3]);
            if (n   >= VV) { e0 = 0.f; e2 = 0.f; }
            if (n+1 >= VV) { e1 = 0.f; e3 = 0.f; }
            rs0 += e0 + e1;
            rs1 += e2 + e3;
            *(__nv_bfloat162*)&d_elogh[(size_t)row0*VP + n] =
                __floats2bfloat162_rn(e0, e1);
            *(__nv_bfloat162*)&d_elogh[(size_t)(row0+8)*VP + n] =
                __floats2bfloat162_rn(e2, e3);
        }
        rs0 += __shfl_xor_sync(0xffffffffu, rs0, 1);
        rs0 += __shfl_xor_sync(0xffffffffu, rs0, 2);
        rs1 += __shfl_xor_sync(0xffffffffu, rs1, 1);
        rs1 += __shfl_xor_sync(0xffffffffu, rs1, 2);
        if (t == 0) {
            atomicAdd(&d_rowsum[row0],     rs0);
            atomicAdd(&d_rowsum[row0 + 8], rs1);
        }
    }
}

__global__ void k_addbias(const float* __restrict__ b_map) {
    int i = blockIdx.x * blockDim.x + threadIdx.x;
    if (i < TT*EHH) d_x[i] += b_map[i % EHH];
}

// ------------- LSTM input gates (parallel over t) -------------
__global__ void k_gin(const float* __restrict__ Wih, const float* __restrict__ bih,
                      const float* __restrict__ bhh, const float* __restrict__ x, int l) {
    int w = (blockIdx.x * blockDim.x + threadIdx.x) >> 5;
    int lane = threadIdx.x & 31;
    if (w >= TT*4*EHH) return;
    int t = w / (4*EHH), r = w % (4*EHH);
    const float* wr = Wih + (size_t)l*4*EHH*EHH + (size_t)r*EHH;
    const float* xr = x + t*EHH;
    float s = 0.f;
    for (int j = lane; j < EHH; j += 32) s += wr[j]*xr[j];
    s = warp_sum(s);
    if (lane == 0) d_gin[t*4*EHH + r] = s + bih[l*4*EHH + r] + bhh[l*4*EHH + r];
}

// ------------- LSTM recurrence: NBLK persistent blocks, smem-resident Whh -------------
__global__ void __launch_bounds__(256, 1) k_lstm8(
        const float* __restrict__ Whh, float* __restrict__ yout, int l) {
    extern __shared__ float dynsm[];
    float* Wsm  = dynsm;
    float* h_sm = Wsm + LROWS*LSTR;
    float* gacc = h_sm + EHH;
    float* gsum = gacc + 2*LROWS;
    const int tid = threadIdx.x, b = blockIdx.x;

    for (int idx = tid; idx < LROWS*EHH; idx += 256) {
        int row = idx / EHH, col = idx % EHH;
        int q = row / HSL, j = row % HSL;
        int grow = q*EHH + b*HSL + j;
        Wsm[row*LSTR + col] = Whh[(size_t)l*4*EHH*EHH + (size_t)grow*EHH + col];
    }
    float c = 0.f;
    if (tid < HSL) d_hbuf2[0][b*HSL + tid] = 0.f;
    __threadfence();
    __syncthreads();
    if (tid == 0) atomicAdd(&d_syncv[l], 1u);
    if (tid == 0) {
        volatile unsigned int* p = &d_syncv[l];
        while (*p < NBLK) { }
    }
    __syncthreads();

    const int myrow = tid % LROWS;
    const int myhalf = tid / LROWS;

    for (int t = 0; t < TT; t++) {
        if (tid < EHH) h_sm[tid] = ((volatile float*)d_hbuf2[t & 1])[tid];
        __syncthreads();
        if (tid < 2*LROWS) {
            const float4* w4 = (const float4*)(Wsm + myrow*LSTR + myhalf*100);
            const float4* h4 = (const float4*)(h_sm + myhalf*100);
            float acc = 0.f;
#pragma unroll
            for (int jj = 0; jj < 25; jj++) {
                float4 wv = w4[jj], hv = h4[jj];
                acc += wv.x*hv.x + wv.y*hv.y + wv.z*hv.z + wv.w*hv.w;
            }
            gacc[myhalf*LROWS + myrow] = acc;
        }
        __syncthreads();
        if (tid < LROWS) {
            int q = tid / HSL, j = tid % HSL;
            gsum[tid] = gacc[tid] + gacc[LROWS + tid]
                      + d_gin[t*4*EHH + q*EHH + b*HSL + j];
        }
        __syncthreads();
        if (tid < HSL) {
            float ig = sigmf(gsum[tid]);
            float fg = sigmf(gsum[HSL + tid]);
            float gg = tanhf(gsum[2*HSL + tid]);
            float og = sigmf(gsum[3*HSL + tid]);
            c = fg*c + ig*gg;
            float h = og*tanhf(c);
            d_hbuf2[(t + 1) & 1][b*HSL + tid] = h;
            yout[t*EHH + b*HSL + tid] = h;
        }
        __threadfence();
        __syncthreads();
        if (tid == 0) atomicAdd(&d_syncv[l], 1u);
        if (t < TT - 1) {
            if (tid == 0) {
                volatile unsigned int* p = &d_syncv[l];
                unsigned int target = (unsigned int)NBLK * (t + 2);
                while (*p < target) { }
            }
            __syncthreads();
        }
    }
}

// ------------- eta chain (sequential over T, 1 block) -------------
__global__ void k_eta(const float* __restrict__ Wmu, const float* __restrict__ bmu,
                      const float* __restrict__ Wls, const float* __restrict__ bls) {
    __shared__ float inp[EHH+KTOP];
    __shared__ float mu_s[KTOP], ls_s[KTOP], eta_s[KTOP];
    int tid = threadIdx.x, lane = tid & 31, wid = tid >> 5;
    float kl_acc = 0.f;
    for (int t = 0; t < TT; t++) {
        if (tid < EHH) inp[tid] = d_y[t*EHH + tid];
        else if (tid < EHH+KTOP) inp[tid] = (t == 0) ? 0.f : eta_s[tid - EHH];
        __syncthreads();
        for (int o = wid; o < 2*KTOP; o += 8) {
            const float* W = (o < KTOP) ? (Wmu + o*(EHH+KTOP)) : (Wls + (o-KTOP)*(EHH+KTOP));
            float s = 0.f;
            for (int j = lane; j < EHH+KTOP; j += 32) s += W[j]*inp[j];
            s = warp_sum(s);
            if (lane == 0) {
                if (o < KTOP) mu_s[o] = s + bmu[o];
                else          ls_s[o-KTOP] = s + bls[o-KTOP];
            }
        }
        __syncthreads();
        if (tid < KTOP) {
            float mu = mu_s[tid], ls = ls_s[tid];
            float term;
            if (t == 0) term = 0.5f*((__expf(ls) + mu*mu)/(1.f+EPSF) - 1.f - ls);
            else {
                float dd = mu - eta_s[tid];
                term = 0.5f*((__expf(ls) + dd*dd)/(DELTAF+EPSF) - 1.f + LOGDF - ls);
            }
            kl_acc += term;
            d_eta[t*KTOP + tid] = mu;
        }
        __syncthreads();
        if (tid < KTOP) eta_s[tid] = mu_s[tid];
        __syncthreads();
    }
    block_add_double(kl_acc, 2);
}

// ------------- theta hidden epilogue -------------
__global__ void k_theta_h(const float* __restrict__ b_theta, const float* __restrict__ W_theta,
                          const int* __restrict__ times) {
    int idx = blockIdx.x * blockDim.x + threadIdx.x;
    if (idx >= BB*THH) return;
    int b = idx / THH, i = idx % THH;
    int tb = times[b];
    float v = d_hth[idx] + b_theta[i];
    const float* wrow = W_theta + (size_t)i*(VV+KTOP) + VV;
    const float* er = d_eta + tb*KTOP;
#pragma unroll 10
    for (int k = 0; k < KTOP; k++) v += er[k]*wrow[k];
    d_hth[idx] = tanhf(v);
}

// ------------- mu_t / ls_t -------------
__global__ void k_theta_muls(const float* __restrict__ Wmu, const float* __restrict__ bmu,
                             const float* __restrict__ Wls, const float* __restrict__ bls) {
    int w = (blockIdx.x * blockDim.x + threadIdx.x) >> 5;
    int lane = threadIdx.x & 31;
    if (w >= BB*2*KTOP) return;
    int b = w / (2*KTOP), q = w % (2*KTOP);
    int kk = q % KTOP;
    bool isls = q >= KTOP;
    const float* W = (isls ? Wls : Wmu) + kk*THH;
    const float* h = d_hth + b*THH;
    float s = 0.f;
    for (int j = lane; j < THH; j += 32) s += W[j]*h[j];
    s = warp_sum(s);
    if (lane == 0) {
        s += (isls ? bls : bmu)[kk];
        (isls ? d_ls_t : d_mu_t)[b*KTOP + kk] = s;
    }
}

// ------------- theta softmax + kl_theta -------------
__global__ void k_theta_softkl(const int* __restrict__ times) {
    __shared__ float mus[KTOP], es[KTOP], red2[2];
    int b = blockIdx.x, tid = threadIdx.x;
    if (tid < KTOP) mus[tid] = d_mu_t[b*KTOP + tid];
    __syncthreads();
    if (tid == 0) {
        float m = -1e30f;
        for (int k = 0; k < KTOP; k++) m = fmaxf(m, mus[k]);
        red2[0] = m;
    }
    __syncthreads();
    if (tid < KTOP) es[tid] = __expf(mus[tid] - red2[0]);
    __syncthreads();
    if (tid == 0) {
        float s = 0.f;
        for (int k = 0; k < KTOP; k++) s += es[k];
        red2[1] = 1.f/s;
    }
    __syncthreads();
    float kl = 0.f;
    if (tid < KTOP) {
        d_theta[b*KTOP + tid] = es[tid]*red2[1];
        float ls = d_ls_t[b*KTOP + tid];
        float e  = d_eta[times[b]*KTOP + tid];
        float dmu = mus[tid] - e;
        kl = 0.5f*((__expf(ls) + dmu*dmu)/(1.f+EPSF) - 1.f - ls);
    }
    block_add_double(kl, 3);
}

// ------------- kl_alpha -------------
__global__ void k_klalpha(const float* __restrict__ mq, const float* __restrict__ lsq) {
    int idx = blockIdx.x * blockDim.x + threadIdx.x;
    float term = 0.f;
    if (idx < KTOP*TT*EE) {
        int t = (idx / EE) % TT;
        float mu = mq[idx], ls = lsq[idx];
        if (t == 0) term = 0.5f*((__expf(ls) + mu*mu)/(1.f+EPSF) - 1.f - ls);
        else {
            float d = mu - mq[idx - EE];
            term = 0.5f*((__expf(ls) + d*d)/(DELTAF+EPSF) - 1.f + LOGDF - ls);
        }
    }
    block_add_double(term, 1);
}

// ------------- nll -------------
__global__ void k_nll(const float* __restrict__ bows, const int* __restrict__ times) {
    __shared__ float wsh[KTOP];
    int b = blockIdx.x;
    int t = times[b];
    int tid = threadIdx.x;
    if (tid < KTOP) {
        int row = t*KTOP + tid;
        wsh[tid] = d_theta[b*KTOP + tid] / d_rowsum[row];
    }
    __syncthreads();
    int v = blockIdx.y * 256 + tid;
    float val = 0.f;
    if (v < VV) {
        const __nv_bfloat16* base = d_elogh + (size_t)(t*KTOP)*VP + v;
        float p = 0.f;
#pragma unroll 10
        for (int k = 0; k < KTOP; k++)
            p += wsh[k] * __bfloat162float(base[(size_t)k*VP]);
        val = __logf(p + EPSF) * bows[(size_t)b*VV + v];
    }
    block_add_double(val, 0);
}

// ------------- finalize -------------
__global__ void k_finalize(float* out, int n) {
    if (threadIdx.x == 0) {
        float nll = -(float)d_scald[0];
        float ka = (float)d_scald[1];
        float ke = (float)d_scald[2];
        float kt = (float)d_scald[3];
        float vals[5] = {nll + ka + ke + kt, nll, ka, ke, kt};
        for (int i = 0; i < n; i++) out[i] = (i < 5) ? vals[i] : 0.f;
    }
}

extern "C" void kernel_launch(void* const* d_in, const int* in_sizes, int n_in,
                              void* d_out, int out_size) {
    const float* bows      = (const float*)d_in[0];
    const float* nbows     = (const float*)d_in[1];
    const float* rnn_inp   = (const float*)d_in[2];
    const float* word_emb  = (const float*)d_in[3];
    const float* mu_q_a    = (const float*)d_in[4];
    const float* ls_q_a    = (const float*)d_in[5];
    const float* W_theta   = (const float*)d_in[6];
    const float* b_theta   = (const float*)d_in[7];
    const float* W_mu_th   = (const float*)d_in[8];
    const float* b_mu_th   = (const float*)d_in[9];
    const float* W_ls_th   = (const float*)d_in[10];
    const float* b_ls_th   = (const float*)d_in[11];
    const float* W_map     = (const float*)d_in[12];
    const float* b_map     = (const float*)d_in[13];
    const float* lstm_Wih  = (const float*)d_in[14];
    const float* lstm_Whh  = (const float*)d_in[15];
    const float* lstm_bih  = (const float*)d_in[16];
    const float* lstm_bhh  = (const float*)d_in[17];
    const float* W_mu_eta  = (const float*)d_in[18];
    const float* b_mu_eta  = (const float*)d_in[19];
    const float* W_ls_eta  = (const float*)d_in[20];
    const float* b_ls_eta  = (const float*)d_in[21];
    const int*   times     = (const int*)d_in[22];
    float* out = (float*)d_out;

    float *dx, *dy, *dhth;
    cudaGetSymbolAddress((void**)&dx, d_x);
    cudaGetSymbolAddress((void**)&dy, d_y);
    cudaGetSymbolAddress((void**)&dhth, d_hth);

    const int mma_smem  = 2 * 128 * SMS32 * 4;
    const int lstm_smem = (LROWS*LSTR + EHH + 2*LROWS + LROWS) * 4;

    static cudaStream_t s2 = nullptr;
    static cudaEvent_t evA = nullptr, evB = nullptr;
    if (s2 == nullptr) {
        cudaFuncSetAttribute(k_gemm_mma,
            cudaFuncAttributeMaxDynamicSharedMemorySize, mma_smem);
        cudaFuncSetAttribute(k_lstm8,
            cudaFuncAttributeMaxDynamicSharedMemorySize, lstm_smem);
        cudaStreamCreateWithFlags(&s2, cudaStreamNonBlocking);
        cudaEventCreateWithFlags(&evA, cudaEventDisableTiming);
        cudaEventCreateWithFlags(&evB, cudaEventDisableTiming);
    }

    // -------- stream 0: zero, then fork --------
    k_zero<<<(BB*THH + 255)/256, 256>>>();
    cudaEventRecord(evA, 0);
    cudaStreamWaitEvent(s2, evA, 0);

    // -------- side stream: chip-wide independent work --------
    k_alphaT<<<(MP*EP + 255)/256, 256, 0, s2>>>(mu_q_a);
    k_wembpad<<<(int)(((size_t)VP*EP + 255)/256), 256, 0, s2>>>(word_emb);
    {   // hth = nbows @ W_theta[:, :V]^T via tf32 MMA split-K
        dim3 g((THH + 127)/128, 1, TZ);
        k_gemm_tf32<<<g, 256, 0, s2>>>(nbows, VV, BB, W_theta, VV + KTOP, THH,
                                       dhth, THH);
    }
    k_klalpha<<<(KTOP*TT*EE + 255)/256, 256, 0, s2>>>(mu_q_a, ls_q_a);
    {   // logits: bf16 tensor-core GEMM with exp+rowsum epilogue
        dim3 g(VP/128, MP/128);
        k_gemm_mma<<<g, 256, mma_smem, s2>>>();
    }
    cudaEventRecord(evB, s2);

    // -------- stream 0: serial LSTM/eta chain (overlapped with s2) --------
    {   // x = rnn_inp @ W_map^T : M=40, N=200, K=30000, split-K z=25
        dim3 g((EHH + 63)/64, (TT + 63)/64, 25);
        k_sgemm_atomic<<<g, 256>>>(rnn_inp, VV, W_map, VV, dx, TT, EHH, 1200);
    }
    k_addbias<<<(TT*EHH + 255)/256, 256>>>(b_map);

    float* lin = dx; float* lout = dy;
    for (int l = 0; l < LL; l++) {
        k_gin<<<(TT*4*EHH*32 + 255)/256, 256>>>(lstm_Wih, lstm_bih, lstm_bhh, lin, l);
        k_lstm8<<<NBLK, 256, lstm_smem>>>(lstm_Whh, lout, l);
        float* tmp = lin; lin = lout; lout = tmp;
    }

    k_eta<<<1, 256>>>(W_mu_eta, b_mu_eta, W_ls_eta, b_ls_eta);

    // -------- join --------
    cudaStreamWaitEvent(0, evB, 0);

    k_theta_h<<<(BB*THH + 255)/256, 256>>>(b_theta, W_theta, times);
    k_theta_muls<<<(BB*2*KTOP*32 + 255)/256, 256>>>(W_mu_th, b_mu_th, W_ls_th, b_ls_th);
    k_theta_softkl<<<BB, 64>>>(times);

    {
        dim3 g(BB, (VV + 255)/256);
        k_nll<<<g, 256>>>(bows, times);
    }

    k_finalize<<<1, 32>>>(out, out_size);
}

// round 16
// speedup vs baseline: 1.1117x; 1.1117x over previous
#include <cuda_runtime.h>
#include <cuda_bf16.h>
#include <math.h>

#define KTOP 50
#define TT   40
#define VV   30000
#define VP   30080          // 235*128
#define THH  800
#define EHH  200
#define EE   300
#define EP   304            // padded E (multiple of 8, = 19*16)
#define LL   3
#define BB   100
#define MP   2048           // padded logits rows (16*128), real rows = 2000

#define EPSF   1e-6f
#define DELTAF 0.005f
#define LOGDF  -5.2983173665480363f

#define SMS32 156           // mma smem row stride in 32-bit words (= 312 bf16)

// LSTM cluster kernel config
#define NBLK 8
#define HSL  (EHH/NBLK)     // 25
#define LROWS (4*HSL)       // 100
#define LSTR 204
#define HBPAD 52            // hbuf region padded to multiple of 4 floats (16B)

// tf32 theta GEMM config
#define TZ   75
#define TKC  400
#define TSTR 20

// ------------- static device scratch -------------
__device__ float  d_x[TT*EHH];
__device__ float  d_y[TT*EHH];
__device__ float  d_gin[TT*4*EHH];
__device__ float  d_eta[TT*KTOP];
__device__ __nv_bfloat16 d_alphab[MP*EP];
__device__ __nv_bfloat16 d_wembb[(size_t)VP*EP];
__device__ float  d_hth[BB*THH];
__device__ float  d_mu_t[BB*KTOP];
__device__ float  d_ls_t[BB*KTOP];
__device__ float  d_theta[BB*KTOP];
__device__ float  d_rowsum[MP];
__device__ double d_scald[4];
__device__ __nv_bfloat16 d_elogh[(size_t)MP*VP];

// ------------- helpers -------------
__device__ __forceinline__ float warp_sum(float v) {
#pragma unroll
    for (int o = 16; o; o >>= 1) v += __shfl_xor_sync(0xffffffffu, v, o);
    return v;
}
__device__ __forceinline__ float sigmf(float x) { return 1.f / (1.f + __expf(-x)); }
__device__ __forceinline__ unsigned int f2tf32(float v) {
    unsigned int u;
    asm("cvt.rna.tf32.f32 %0, %1;" : "=r"(u) : "f"(v));
    return u;
}
__device__ __forceinline__ unsigned int smem_u32(const void* p) {
    unsigned int a;
    asm("{ .reg .u64 t; cvta.to.shared.u64 t, %1; cvt.u32.u64 %0, t; }"
        : "=r"(a) : "l"(p));
    return a;
}
__device__ __forceinline__ unsigned int mapa_smem(unsigned int addr, unsigned int rank) {
    unsigned int r;
    asm("mapa.shared::cluster.u32 %0, %1, %2;" : "=r"(r) : "r"(addr), "r"(rank));
    return r;
}
__device__ __forceinline__ float ld_dsmem(unsigned int addr) {
    float v;
    asm volatile("ld.shared::cluster.f32 %0, [%1];" : "=f"(v) : "r"(addr));
    return v;
}
#define CLUSTER_SYNC_() do { \
    asm volatile("barrier.cluster.arrive.aligned;" ::: "memory"); \
    asm volatile("barrier.cluster.wait.aligned;" ::: "memory"); \
} while (0)

__device__ __forceinline__ void block_add_double(float v, int slot) {
    __shared__ float red[8];
    int lane = threadIdx.x & 31, wid = threadIdx.x >> 5;
    v = warp_sum(v);
    if (lane == 0) red[wid] = v;
    __syncthreads();
    if (threadIdx.x == 0) {
        float tot = 0.f;
        int nw = (blockDim.x + 31) >> 5;
        for (int w = 0; w < nw; w++) tot += red[w];
        atomicAdd(&d_scald[slot], (double)tot);
    }
}

// ------------- zero -------------
__global__ void k_zero() {
    int i = blockIdx.x * blockDim.x + threadIdx.x;
    if (i < BB*THH) d_hth[i] = 0.f;
    if (i < TT*EHH) d_x[i] = 0.f;
    if (i < MP)     d_rowsum[i] = 0.f;
    if (i < 4)      d_scald[i] = 0.0;
}

// ------------- bf16 conversions -------------
__global__ void k_alphaT(const float* __restrict__ mq) {
    int idx = blockIdx.x * blockDim.x + threadIdx.x;
    if (idx >= MP*EP) return;
    int row = idx / EP, e = idx % EP;
    int t = row / KTOP, k = row % KTOP;
    float v = (row < TT*KTOP && e < EE) ? mq[(k*TT + t)*EE + e] : 0.f;
    d_alphab[idx] = __float2bfloat16_rn(v);
}
__global__ void k_wembpad(const float* __restrict__ we) {
    size_t idx = (size_t)blockIdx.x * blockDim.x + threadIdx.x;
    if (idx >= (size_t)VP*EP) return;
    int v = (int)(idx / EP), e = (int)(idx % EP);
    float x = (v < VV && e < EE) ? we[(size_t)v*EE + e] : 0.f;
    d_wembb[idx] = __float2bfloat16_rn(x);
}

// ------------- generic split-K SGEMM (W_map path) -------------
__global__ void __launch_bounds__(256) k_sgemm_atomic(
        const float* __restrict__ A, int lda,
        const float* __restrict__ B, int ldb,
        float* __restrict__ C, int M, int N, int kchunk) {
    __shared__ float As[8][64];
    __shared__ float Bs[8][64];
    const int k0b = blockIdx.z * kchunk;
    const int bm = blockIdx.y * 64, bn = blockIdx.x * 64;
    const int tid = threadIdx.x;
    const int lr = tid >> 2, lk = (tid & 3) * 2;
    const int tx = tid & 15, ty = tid >> 4;
    float acc[4][4];
#pragma unroll
    for (int i = 0; i < 4; i++)
#pragma unroll
        for (int j = 0; j < 4; j++) acc[i][j] = 0.f;

    const int kend = k0b + kchunk;
    for (int k0 = k0b; k0 < kend; k0 += 8) {
        float2 av = make_float2(0.f,0.f), bv = make_float2(0.f,0.f);
        int am = bm + lr, bn2 = bn + lr;
        if (am < M) av = *(const float2*)&A[(size_t)am*lda + k0 + lk];
        if (bn2 < N) bv = *(const float2*)&B[(size_t)bn2*ldb + k0 + lk];
        As[lk][lr] = av.x; As[lk+1][lr] = av.y;
        Bs[lk][lr] = bv.x; Bs[lk+1][lr] = bv.y;
        __syncthreads();
#pragma unroll
        for (int kk = 0; kk < 8; kk++) {
            float a[4], b[4];
            *(float4*)a = *(const float4*)&As[kk][ty*4];
            *(float4*)b = *(const float4*)&Bs[kk][tx*4];
#pragma unroll
            for (int i = 0; i < 4; i++)
#pragma unroll
                for (int j = 0; j < 4; j++) acc[i][j] += a[i]*b[j];
        }
        __syncthreads();
    }
#pragma unroll
    for (int i = 0; i < 4; i++) {
        int m = bm + ty*4 + i;
        if (m >= M) continue;
#pragma unroll
        for (int j = 0; j < 4; j++) {
            int n = bn + tx*4 + j;
            if (n < N) atomicAdd(&C[(size_t)m*N + n], acc[i][j]);
        }
    }
}

// ------------- tf32 MMA split-K GEMM (theta path) -------------
__global__ void __launch_bounds__(256, 2) k_gemm_tf32(
        const float* __restrict__ A, int lda, int M,
        const float* __restrict__ B, int ldb, int N,
        float* __restrict__ C, int ldc) {
    __shared__ float sA[128*TSTR];
    __shared__ float sB[128*TSTR];
    const int tid = threadIdx.x;
    const int bn = blockIdx.x * 128;
    const int kk0 = (int)blockIdx.z * TKC;

    const int w = tid >> 5;
    const int wm = w & 1;
    const int wn = w >> 1;
    const int lane = tid & 31;
    const int g = lane >> 2;
    const int t = lane & 3;

    float c[4][4][4];
#pragma unroll
    for (int mt = 0; mt < 4; mt++)
#pragma unroll
        for (int nt = 0; nt < 4; nt++)
#pragma unroll
            for (int q = 0; q < 4; q++) c[mt][nt][q] = 0.f;

    const int lrow = tid >> 2;
    const int lq   = (tid & 3) * 4;

    for (int it = 0; it < TKC/16; it++) {
        const int k0 = kk0 + it*16;
#pragma unroll
        for (int rep = 0; rep < 2; rep++) {
            int row = lrow + rep*64;
            float4 av = make_float4(0.f,0.f,0.f,0.f);
            float4 bv = make_float4(0.f,0.f,0.f,0.f);
            if (row < M)      av = *(const float4*)&A[(size_t)row*lda + k0 + lq];
            if (bn + row < N) {
                const float* bp = &B[(size_t)(bn + row)*ldb + k0 + lq];
                float2 u = *(const float2*)bp;
                float2 v2 = *(const float2*)(bp + 2);
                bv = make_float4(u.x, u.y, v2.x, v2.y);
            }
            *(float4*)&sA[row*TSTR + lq] = av;
            *(float4*)&sB[row*TSTR + lq] = bv;
        }
        __syncthreads();
#pragma unroll
        for (int ks = 0; ks < 16; ks += 8) {
            unsigned int af[4][4], bf[4][2];
#pragma unroll
            for (int mt = 0; mt < 4; mt++) {
                int base = (wm*64 + mt*16 + g)*TSTR + ks + t;
                af[mt][0] = f2tf32(sA[base]);
                af[mt][1] = f2tf32(sA[base + 8*TSTR]);
                af[mt][2] = f2tf32(sA[base + 4]);
                af[mt][3] = f2tf32(sA[base + 8*TSTR + 4]);
            }
#pragma unroll
            for (int nt = 0; nt < 4; nt++) {
                int base = (wn*32 + nt*8 + g)*TSTR + ks + t;
                bf[nt][0] = f2tf32(sB[base]);
                bf[nt][1] = f2tf32(sB[base + 4]);
            }
#pragma unroll
            for (int mt = 0; mt < 4; mt++)
#pragma unroll
                for (int nt = 0; nt < 4; nt++)
                    asm volatile(
                        "mma.sync.aligned.m16n8k8.row.col.f32.tf32.tf32.f32 "
                        "{%0,%1,%2,%3}, {%4,%5,%6,%7}, {%8,%9}, {%0,%1,%2,%3};"
                        : "+f"(c[mt][nt][0]), "+f"(c[mt][nt][1]),
                          "+f"(c[mt][nt][2]), "+f"(c[mt][nt][3])
                        : "r"(af[mt][0]), "r"(af[mt][1]), "r"(af[mt][2]), "r"(af[mt][3]),
                          "r"(bf[nt][0]), "r"(bf[nt][1]));
        }
        __syncthreads();
    }

#pragma unroll
    for (int mt = 0; mt < 4; mt++) {
        int m0 = wm*64 + mt*16 + g;
#pragma unroll
        for (int nt = 0; nt < 4; nt++) {
            int n0 = bn + wn*32 + nt*8 + 2*t;
            if (m0 < M) {
                if (n0   < N) atomicAdd(&C[(size_t)m0*ldc + n0],   c[mt][nt][0]);
                if (n0+1 < N) atomicAdd(&C[(size_t)m0*ldc + n0+1], c[mt][nt][1]);
            }
            if (m0 + 8 < M) {
                if (n0   < N) atomicAdd(&C[(size_t)(m0+8)*ldc + n0],   c[mt][nt][2]);
                if (n0+1 < N) atomicAdd(&C[(size_t)(m0+8)*ldc + n0+1], c[mt][nt][3]);
            }
        }
    }
}

// ------------- bf16 HMMA logits GEMM: 128x128 tile, exp->bf16 + rowsum -------------
__global__ void __launch_bounds__(256, 1) k_gemm_mma() {
    extern __shared__ unsigned int smw[];
    unsigned int* sA = smw;
    unsigned int* sB = smw + 128*SMS32;
    const int tid = threadIdx.x;
    const int bm = blockIdx.y * 128, bn = blockIdx.x * 128;

    {
        const uint4* gA = (const uint4*)(d_alphab + (size_t)bm*EP);
        const uint4* gB = (const uint4*)(d_wembb + (size_t)bn*EP);
        uint4* s4A = (uint4*)sA;
        uint4* s4B = (uint4*)sB;
        for (int i = tid; i < 128*38; i += 256) {
            int row = i / 38, c = i % 38;
            s4A[row*39 + c] = gA[row*38 + c];
            s4B[row*39 + c] = gB[row*38 + c];
        }
    }
    __syncthreads();

    const int w   = tid >> 5;
    const int wm  = w & 1;
    const int wn  = w >> 1;
    const int lane = tid & 31;
    const int g = lane >> 2;
    const int t = lane & 3;

    float c[4][4][4];
#pragma unroll
    for (int mt = 0; mt < 4; mt++)
#pragma unroll
        for (int nt = 0; nt < 4; nt++)
#pragma unroll
            for (int q = 0; q < 4; q++) c[mt][nt][q] = 0.f;

    const unsigned int* sAb = sA + (wm*64 + g)*SMS32 + t;
    const unsigned int* sBb = sB + (wn*32 + g)*SMS32 + t;

    for (int kk = 0; kk < EP/16; kk++) {
        const int ko = kk*8;
        unsigned int a[4][4], b[4][2];
#pragma unroll
        for (int mt = 0; mt < 4; mt++) {
            const unsigned int* p = sAb + mt*16*SMS32 + ko;
            a[mt][0] = p[0];
            a[mt][1] = p[8*SMS32];
            a[mt][2] = p[4];
            a[mt][3] = p[8*SMS32 + 4];
        }
#pragma unroll
        for (int nt = 0; nt < 4; nt++) {
            const unsigned int* p = sBb + nt*8*SMS32 + ko;
            b[nt][0] = p[0];
            b[nt][1] = p[4];
        }
#pragma unroll
        for (int mt = 0; mt < 4; mt++)
#pragma unroll
            for (int nt = 0; nt < 4; nt++)
                asm volatile(
                    "mma.sync.aligned.m16n8k16.row.col.f32.bf16.bf16.f32 "
                    "{%0,%1,%2,%3}, {%4,%5,%6,%7}, {%8,%9}, {%0,%1,%2,%3};"
                    : "+f"(c[mt][nt][0]), "+f"(c[mt][nt][1]),
                      "+f"(c[mt][nt][2]), "+f"(c[mt][nt][3])
                    : "r"(a[mt][0]), "r"(a[mt][1]), "r"(a[mt][2]), "r"(a[mt][3]),
                      "r"(b[nt][0]), "r"(b[nt][1]));
    }

#pragma unroll
    for (int mt = 0; mt < 4; mt++) {
        float rs0 = 0.f, rs1 = 0.f;
        int row0 = bm + wm*64 + mt*16 + g;
#pragma unroll
        for (int nt = 0; nt < 4; nt++) {
            int n = bn + wn*32 + nt*8 + t*2;
            float e0 = __expf(c[mt][nt][0]);
            float e1 = __expf(c[mt][nt][1]);
            float e2 = __expf(c[mt][nt][2]);
            float e3 = __expf(c[mt][nt][3]);
            if (n   >= VV) { e0 = 0.f; e2 = 0.f; }
            if (n+1 >= VV) { e1 = 0.f; e3 = 0.f; }
            rs0 += e0 + e1;
            rs1 += e2 + e3;
            *(__nv_bfloat162*)&d_elogh[(size_t)row0*VP + n] =
                __floats2bfloat162_rn(e0, e1);
            *(__nv_bfloat162*)&d_elogh[(size_t)(row0+8)*VP + n] =
                __floats2bfloat162_rn(e2, e3);
        }
        rs0 += __shfl_xor_sync(0xffffffffu, rs0, 1);
        rs0 += __shfl_xor_sync(0xffffffffu, rs0, 2);
        rs1 += __shfl_xor_sync(0xffffffffu, rs1, 1);
        rs1 += __shfl_xor_sync(0xffffffffu, rs1, 2);
        if (t == 0) {
            atomicAdd(&d_rowsum[row0],     rs0);
            atomicAdd(&d_rowsum[row0 + 8], rs1);
        }
    }
}

__global__ void k_addbias(const float* __restrict__ b_map) {
    int i = blockIdx.x * blockDim.x + threadIdx.x;
    if (i < TT*EHH) d_x[i] += b_map[i % EHH];
}

// ------------- LSTM input gates (parallel over t) -------------
__global__ void k_gin(const float* __restrict__ Wih, const float* __restrict__ bih,
                      const float* __restrict__ bhh, const float* __restrict__ x, int l) {
    int w = (blockIdx.x * blockDim.x + threadIdx.x) >> 5;
    int lane = threadIdx.x & 31;
    if (w >= TT*4*EHH) return;
    int t = w / (4*EHH), r = w % (4*EHH);
    const float* wr = Wih + (size_t)l*4*EHH*EHH + (size_t)r*EHH;
    const float* xr = x + t*EHH;
    float s = 0.f;
    for (int j = lane; j < EHH; j += 32) s += wr[j]*xr[j];
    s = warp_sum(s);
    if (lane == 0) d_gin[t*4*EHH + r] = s + bih[l*4*EHH + r] + bhh[l*4*EHH + r];
}

// ------------- LSTM recurrence: 8-CTA cluster, smem Whh, DSMEM h exchange -------------
// Block b owns h elements [b*25,(b+1)*25); per step: one cluster barrier,
// h gathered from peers' smem hbuf (double-buffered).
// smem layout (floats): Wsm[20400] | hbuf[HBPAD=52] | h_sm[200] | gacc[200] | gsum[100]
// h_sm offset 20452 (mult of 4) -> float4 loads stay 16B-aligned.
__global__ void __launch_bounds__(256, 1) __cluster_dims__(NBLK, 1, 1)
k_lstm_cl(const float* __restrict__ Whh, float* __restrict__ yout, int l) {
    extern __shared__ float dynsm[];
    float* Wsm  = dynsm;                    // [LROWS][LSTR]
    float* hbuf = Wsm + LROWS*LSTR;         // [2][HSL] own slice (padded region)
    float* h_sm = hbuf + HBPAD;             // [EHH] gathered h (16B aligned)
    float* gacc = h_sm + EHH;               // [2][LROWS]
    float* gsum = gacc + 2*LROWS;           // [LROWS]
    const int tid = threadIdx.x;
    const int b = blockIdx.x;               // == cluster rank (grid = NBLK)

    for (int idx = tid; idx < LROWS*EHH; idx += 256) {
        int row = idx / EHH, col = idx % EHH;
        int q = row / HSL, j = row % HSL;
        int grow = q*EHH + b*HSL + j;
        Wsm[row*LSTR + col] = Whh[(size_t)l*4*EHH*EHH + (size_t)grow*EHH + col];
    }
    if (tid < EHH) h_sm[tid] = 0.f;         // h(0) = 0
    float c = 0.f;
    __syncthreads();

    const unsigned int hbuf_addr = smem_u32(hbuf);
    const int myrow = tid % LROWS;
    const int myhalf = tid / LROWS;
    const int src_cta = tid / HSL;          // for gather (tid < EHH)
    const int src_j   = tid % HSL;

    for (int t = 0; t < TT; t++) {
        // gate accumulation: 200 threads, each half-dot of 100
        if (tid < 2*LROWS) {
            const float4* w4 = (const float4*)(Wsm + myrow*LSTR + myhalf*100);
            const float4* h4 = (const float4*)(h_sm + myhalf*100);
            float acc = 0.f;
#pragma unroll
            for (int jj = 0; jj < 25; jj++) {
                float4 wv = w4[jj], hv = h4[jj];
                acc += wv.x*hv.x + wv.y*hv.y + wv.z*hv.z + wv.w*hv.w;
            }
            gacc[myhalf*LROWS + myrow] = acc;
        }
        __syncthreads();
        if (tid < LROWS) {
            int q = tid / HSL, j = tid % HSL;
            gsum[tid] = gacc[tid] + gacc[LROWS + tid]
                      + d_gin[t*4*EHH + q*EHH + b*HSL + j];
        }
        __syncthreads();
        if (tid < HSL) {
            float ig = sigmf(gsum[tid]);
            float fg = sigmf(gsum[HSL + tid]);
            float gg = tanhf(gsum[2*HSL + tid]);
            float og = sigmf(gsum[3*HSL + tid]);
            c = fg*c + ig*gg;
            float h = og*tanhf(c);
            hbuf[((t + 1) & 1)*HSL + tid] = h;
            yout[t*EHH + b*HSL + tid] = h;
        }
        CLUSTER_SYNC_();                    // peers' hbuf slices now visible
        if (t < TT - 1) {
            if (tid < EHH) {
                unsigned int pa = mapa_smem(
                    hbuf_addr + (((t + 1) & 1)*HSL + src_j)*4u, (unsigned int)src_cta);
                h_sm[tid] = ld_dsmem(pa);
            }
            __syncthreads();
        }
    }
    CLUSTER_SYNC_();                        // no CTA exits while peers may read
}

// ------------- eta chain: smem-resident weights, sequential over T -------------
__global__ void k_eta(const float* __restrict__ Wmu, const float* __restrict__ bmu,
                      const float* __restrict__ Wls, const float* __restrict__ bls) {
    extern __shared__ float sW[];           // [100][250]: rows 0-49 mu, 50-99 ls
    __shared__ float inp[EHH+KTOP];
    __shared__ float mu_s[KTOP], ls_s[KTOP], eta_s[KTOP];
    int tid = threadIdx.x, lane = tid & 31, wid = tid >> 5;
    const int IN = EHH + KTOP;              // 250

    for (int i = tid; i < KTOP*IN; i += 256) sW[i] = Wmu[i];
    for (int i = tid; i < KTOP*IN; i += 256) sW[KTOP*IN + i] = Wls[i];
    __syncthreads();

    float kl_acc = 0.f;
    for (int t = 0; t < TT; t++) {
        if (tid < EHH) inp[tid] = d_y[t*EHH + tid];
        else if (tid < IN) inp[tid] = (t == 0) ? 0.f : eta_s[tid - EHH];
        __syncthreads();
        for (int o = wid; o < 2*KTOP; o += 8) {
            const float* W = sW + o*IN;
            float s = 0.f;
            for (int j = lane; j < IN; j += 32) s += W[j]*inp[j];
            s = warp_sum(s);
            if (lane == 0) {
                if (o < KTOP) mu_s[o] = s + bmu[o];
                else          ls_s[o-KTOP] = s + bls[o-KTOP];
            }
        }
        __syncthreads();
        if (tid < KTOP) {
            float mu = mu_s[tid], ls = ls_s[tid];
            float term;
            if (t == 0) term = 0.5f*((__expf(ls) + mu*mu)/(1.f+EPSF) - 1.f - ls);
            else {
                float dd = mu - eta_s[tid];
                term = 0.5f*((__expf(ls) + dd*dd)/(DELTAF+EPSF) - 1.f + LOGDF - ls);
            }
            kl_acc += term;
            d_eta[t*KTOP + tid] = mu;
        }
        __syncthreads();
        if (tid < KTOP) eta_s[tid] = mu_s[tid];
        __syncthreads();
    }
    block_add_double(kl_acc, 2);
}

// ------------- theta hidden epilogue -------------
__global__ void k_theta_h(const float* __restrict__ b_theta, const float* __restrict__ W_theta,
                          const int* __restrict__ times) {
    int idx = blockIdx.x * blockDim.x + threadIdx.x;
    if (idx >= BB*THH) return;
    int b = idx / THH, i = idx % THH;
    int tb = times[b];
    float v = d_hth[idx] + b_theta[i];
    const float* wrow = W_theta + (size_t)i*(VV+KTOP) + VV;
    const float* er = d_eta + tb*KTOP;
#pragma unroll 10
    for (int k = 0; k < KTOP; k++) v += er[k]*wrow[k];
    d_hth[idx] = tanhf(v);
}

// ------------- mu_t / ls_t -------------
__global__ void k_theta_muls(const float* __restrict__ Wmu, const float* __restrict__ bmu,
                             const float* __restrict__ Wls, const float* __restrict__ bls) {
    int w = (blockIdx.x * blockDim.x + threadIdx.x) >> 5;
    int lane = threadIdx.x & 31;
    if (w >= BB*2*KTOP) return;
    int b = w / (2*KTOP), q = w % (2*KTOP);
    int kk = q % KTOP;
    bool isls = q >= KTOP;
    const float* W = (isls ? Wls : Wmu) + kk*THH;
    const float* h = d_hth + b*THH;
    float s = 0.f;
    for (int j = lane; j < THH; j += 32) s += W[j]*h[j];
    s = warp_sum(s);
    if (lane == 0) {
        s += (isls ? bls : bmu)[kk];
        (isls ? d_ls_t : d_mu_t)[b*KTOP + kk] = s;
    }
}

// ------------- theta softmax + kl_theta -------------
__global__ void k_theta_softkl(const int* __restrict__ times) {
    __shared__ float mus[KTOP], es[KTOP], red2[2];
    int b = blockIdx.x, tid = threadIdx.x;
    if (tid < KTOP) mus[tid] = d_mu_t[b*KTOP + tid];
    __syncthreads();
    if (tid == 0) {
        float m = -1e30f;
        for (int k = 0; k < KTOP; k++) m = fmaxf(m, mus[k]);
        red2[0] = m;
    }
    __syncthreads();
    if (tid < KTOP) es[tid] = __expf(mus[tid] - red2[0]);
    __syncthreads();
    if (tid == 0) {
        float s = 0.f;
        for (int k = 0; k < KTOP; k++) s += es[k];
        red2[1] = 1.f/s;
    }
    __syncthreads();
    float kl = 0.f;
    if (tid < KTOP) {
        d_theta[b*KTOP + tid] = es[tid]*red2[1];
        float ls = d_ls_t[b*KTOP + tid];
        float e  = d_eta[times[b]*KTOP + tid];
        float dmu = mus[tid] - e;
        kl = 0.5f*((__expf(ls) + dmu*dmu)/(1.f+EPSF) - 1.f - ls);
    }
    block_add_double(kl, 3);
}

// ------------- kl_alpha -------------
__global__ void k_klalpha(const float* __restrict__ mq, const float* __restrict__ lsq) {
    int idx = blockIdx.x * blockDim.x + threadIdx.x;
    float term = 0.f;
    if (idx < KTOP*TT*EE) {
        int t = (idx / EE) % TT;
        float mu = mq[idx], ls = lsq[idx];
        if (t == 0) term = 0.5f*((__expf(ls) + mu*mu)/(1.f+EPSF) - 1.f - ls);
        else {
            float d = mu - mq[idx - EE];
            term = 0.5f*((__expf(ls) + d*d)/(DELTAF+EPSF) - 1.f + LOGDF - ls);
        }
    }
    block_add_double(term, 1);
}

// ------------- nll -------------
__global__ void k_nll(const float* __restrict__ bows, const int* __restrict__ times) {
    __shared__ float wsh[KTOP];
    int b = blockIdx.x;
    int t = times[b];
    int tid = threadIdx.x;
    if (tid < KTOP) {
        int row = t*KTOP + tid;
        wsh[tid] = d_theta[b*KTOP + tid] / d_rowsum[row];
    }
    __syncthreads();
    int v = blockIdx.y * 256 + tid;
    float val = 0.f;
    if (v < VV) {
        const __nv_bfloat16* base = d_elogh + (size_t)(t*KTOP)*VP + v;
        float p = 0.f;
#pragma unroll 10
        for (int k = 0; k < KTOP; k++)
            p += wsh[k] * __bfloat162float(base[(size_t)k*VP]);
        val = __logf(p + EPSF) * bows[(size_t)b*VV + v];
    }
    block_add_double(val, 0);
}

// ------------- finalize -------------
__global__ void k_finalize(float* out, int n) {
    if (threadIdx.x == 0) {
        float nll = -(float)d_scald[0];
        float ka = (float)d_scald[1];
        float ke = (float)d_scald[2];
        float kt = (float)d_scald[3];
        float vals[5] = {nll + ka + ke + kt, nll, ka, ke, kt};
        for (int i = 0; i < n; i++) out[i] = (i < 5) ? vals[i] : 0.f;
    }
}

extern "C" void kernel_launch(void* const* d_in, const int* in_sizes, int n_in,
                              void* d_out, int out_size) {
    const float* bows      = (const float*)d_in[0];
    const float* nbows     = (const float*)d_in[1];
    const float* rnn_inp   = (const float*)d_in[2];
    const float* word_emb  = (const float*)d_in[3];
    const float* mu_q_a    = (const float*)d_in[4];
    const float* ls_q_a    = (const float*)d_in[5];
    const float* W_theta   = (const float*)d_in[6];
    const float* b_theta   = (const float*)d_in[7];
    const float* W_mu_th   = (const float*)d_in[8];
    const float* b_mu_th   = (const float*)d_in[9];
    const float* W_ls_th   = (const float*)d_in[10];
    const float* b_ls_th   = (const float*)d_in[11];
    const float* W_map     = (const float*)d_in[12];
    const float* b_map     = (const float*)d_in[13];
    const float* lstm_Wih  = (const float*)d_in[14];
    const float* lstm_Whh  = (const float*)d_in[15];
    const float* lstm_bih  = (const float*)d_in[16];
    const float* lstm_bhh  = (const float*)d_in[17];
    const float* W_mu_eta  = (const float*)d_in[18];
    const float* b_mu_eta  = (const float*)d_in[19];
    const float* W_ls_eta  = (const float*)d_in[20];
    const float* b_ls_eta  = (const float*)d_in[21];
    const int*   times     = (const int*)d_in[22];
    float* out = (float*)d_out;

    float *dx, *dy, *dhth;
    cudaGetSymbolAddress((void**)&dx, d_x);
    cudaGetSymbolAddress((void**)&dy, d_y);
    cudaGetSymbolAddress((void**)&dhth, d_hth);

    const int mma_smem  = 2 * 128 * SMS32 * 4;
    const int lstm_smem = (LROWS*LSTR + HBPAD + EHH + 2*LROWS + LROWS) * 4;
    const int eta_smem  = 2 * KTOP * (EHH + KTOP) * 4;   // 100 KB

    static cudaStream_t s2 = nullptr;
    static cudaEvent_t evA = nullptr, evB = nullptr;
    if (s2 == nullptr) {
        cudaFuncSetAttribute(k_gemm_mma,
            cudaFuncAttributeMaxDynamicSharedMemorySize, mma_smem);
        cudaFuncSetAttribute(k_lstm_cl,
            cudaFuncAttributeMaxDynamicSharedMemorySize, lstm_smem);
        cudaFuncSetAttribute(k_eta,
            cudaFuncAttributeMaxDynamicSharedMemorySize, eta_smem);
        cudaStreamCreateWithFlags(&s2, cudaStreamNonBlocking);
        cudaEventCreateWithFlags(&evA, cudaEventDisableTiming);
        cudaEventCreateWithFlags(&evB, cudaEventDisableTiming);
    }

    // -------- stream 0: zero, then fork --------
    k_zero<<<(BB*THH + 255)/256, 256>>>();
    cudaEventRecord(evA, 0);
    cudaStreamWaitEvent(s2, evA, 0);

    // -------- side stream: chip-wide independent work --------
    k_alphaT<<<(MP*EP + 255)/256, 256, 0, s2>>>(mu_q_a);
    k_wembpad<<<(int)(((size_t)VP*EP + 255)/256), 256, 0, s2>>>(word_emb);
    {
        dim3 g((THH + 127)/128, 1, TZ);
        k_gemm_tf32<<<g, 256, 0, s2>>>(nbows, VV, BB, W_theta, VV + KTOP, THH,
                                       dhth, THH);
    }
    k_klalpha<<<(KTOP*TT*EE + 255)/256, 256, 0, s2>>>(mu_q_a, ls_q_a);
    {
        dim3 g(VP/128, MP/128);
        k_gemm_mma<<<g, 256, mma_smem, s2>>>();
    }
    cudaEventRecord(evB, s2);

    // -------- stream 0: serial LSTM/eta chain (overlapped with s2) --------
    {
        dim3 g((EHH + 63)/64, (TT + 63)/64, 25);
        k_sgemm_atomic<<<g, 256>>>(rnn_inp, VV, W_map, VV, dx, TT, EHH, 1200);
    }
    k_addbias<<<(TT*EHH + 255)/256, 256>>>(b_map);

    float* lin = dx; float* lout = dy;
    for (int l = 0; l < LL; l++) {
        k_gin<<<(TT*4*EHH*32 + 255)/256, 256>>>(lstm_Wih, lstm_bih, lstm_bhh, lin, l);
        k_lstm_cl<<<NBLK, 256, lstm_smem>>>(lstm_Whh, lout, l);
        float* tmp = lin; lin = lout; lout = tmp;
    }

    k_eta<<<1, 256, eta_smem>>>(W_mu_eta, b_mu_eta, W_ls_eta, b_ls_eta);

    // -------- join --------
    cudaStreamWaitEvent(0, evB, 0);

    k_theta_h<<<(BB*THH + 255)/256, 256>>>(b_theta, W_theta, times);
    k_theta_muls<<<(BB*2*KTOP*32 + 255)/256, 256>>>(W_mu_th, b_mu_th, W_ls_th, b_ls_th);
    k_theta_softkl<<<BB, 64>>>(times);

    {
        dim3 g(BB, (VV + 255)/256);
        k_nll<<<g, 256>>>(bows, times);
    }

    k_finalize<<<1, 32>>>(out, out_size);
}

// round 17
// speedup vs baseline: 1.1955x; 1.0754x over previous
#include <cuda_runtime.h>
#include <cuda_bf16.h>
#include <math.h>

#define KTOP 50
#define TT   40
#define VV   30000
#define VP   30080          // 235*128
#define THH  800
#define EHH  200
#define EE   300
#define EP   304            // padded E (multiple of 8, = 19*16)
#define LL   3
#define BB   100
#define MP   2048           // padded logits rows (16*128), real rows = 2000

#define EPSF   1e-6f
#define DELTAF 0.005f
#define LOGDF  -5.2983173665480363f

#define SMS32 156           // mma smem row stride in 32-bit words (= 312 bf16)

// LSTM cluster kernel config
#define NBLK 8
#define HSL  (EHH/NBLK)     // 25
#define LROWS (4*HSL)       // 100
#define LSTR 204
#define HBPAD 52            // hbuf region padded (keeps h_sm 16B-aligned)

// tf32 theta GEMM config
#define TZ   25
#define TKC  1200           // 25*1200 = 30000
#define TSTR 20

// nll chunking
#define NVCH 4
#define VCH  7520           // VP/4

// ------------- static device scratch -------------
__device__ float  d_x[TT*EHH];
__device__ float  d_y[TT*EHH];
__device__ float  d_gin[TT*4*EHH];
__device__ float  d_eta[TT*KTOP];
__device__ float  d_etain[TT*2*KTOP];
__device__ __nv_bfloat16 d_alphab[MP*EP];
__device__ __nv_bfloat16 d_wembb[(size_t)VP*EP];
__device__ float  d_hth[BB*THH];
__device__ float  d_mu_t[BB*KTOP];
__device__ float  d_ls_t[BB*KTOP];
__device__ float  d_theta[BB*KTOP];
__device__ float  d_rowsum[MP];
__device__ double d_scald[4];
__device__ __nv_bfloat16 d_elogh[(size_t)MP*VP];

// ------------- helpers -------------
__device__ __forceinline__ float warp_sum(float v) {
#pragma unroll
    for (int o = 16; o; o >>= 1) v += __shfl_xor_sync(0xffffffffu, v, o);
    return v;
}
__device__ __forceinline__ float sigmf(float x) { return 1.f / (1.f + __expf(-x)); }
__device__ __forceinline__ unsigned int f2tf32(float v) {
    unsigned int u;
    asm("cvt.rna.tf32.f32 %0, %1;" : "=r"(u) : "f"(v));
    return u;
}
__device__ __forceinline__ unsigned int smem_u32(const void* p) {
    unsigned int a;
    asm("{ .reg .u64 t; cvta.to.shared.u64 t, %1; cvt.u32.u64 %0, t; }"
        : "=r"(a) : "l"(p));
    return a;
}
__device__ __forceinline__ unsigned int mapa_smem(unsigned int addr, unsigned int rank) {
    unsigned int r;
    asm("mapa.shared::cluster.u32 %0, %1, %2;" : "=r"(r) : "r"(addr), "r"(rank));
    return r;
}
__device__ __forceinline__ float ld_dsmem(unsigned int addr) {
    float v;
    asm volatile("ld.shared::cluster.f32 %0, [%1];" : "=f"(v) : "r"(addr));
    return v;
}
#define CLUSTER_SYNC_() do { \
    asm volatile("barrier.cluster.arrive.aligned;" ::: "memory"); \
    asm volatile("barrier.cluster.wait.aligned;" ::: "memory"); \
} while (0)

__device__ __forceinline__ void block_add_double(float v, int slot) {
    __shared__ float red[8];
    int lane = threadIdx.x & 31, wid = threadIdx.x >> 5;
    v = warp_sum(v);
    if (lane == 0) red[wid] = v;
    __syncthreads();
    if (threadIdx.x == 0) {
        float tot = 0.f;
        int nw = (blockDim.x + 31) >> 5;
        for (int w = 0; w < nw; w++) tot += red[w];
        atomicAdd(&d_scald[slot], (double)tot);
    }
}

// ------------- zero -------------
__global__ void k_zero() {
    int i = blockIdx.x * blockDim.x + threadIdx.x;
    if (i < BB*THH) d_hth[i] = 0.f;
    if (i < TT*EHH) d_x[i] = 0.f;
    if (i < MP)     d_rowsum[i] = 0.f;
    if (i < 4)      d_scald[i] = 0.0;
}

// ------------- bf16 conversions -------------
__global__ void k_alphaT(const float* __restrict__ mq) {
    int idx = blockIdx.x * blockDim.x + threadIdx.x;
    if (idx >= MP*EP) return;
    int row = idx / EP, e = idx % EP;
    int t = row / KTOP, k = row % KTOP;
    float v = (row < TT*KTOP && e < EE) ? mq[(k*TT + t)*EE + e] : 0.f;
    d_alphab[idx] = __float2bfloat16_rn(v);
}
__global__ void k_wembpad(const float* __restrict__ we) {
    size_t idx = (size_t)blockIdx.x * blockDim.x + threadIdx.x;
    if (idx >= (size_t)VP*EP) return;
    int v = (int)(idx / EP), e = (int)(idx % EP);
    float x = (v < VV && e < EE) ? we[(size_t)v*EE + e] : 0.f;
    d_wembb[idx] = __float2bfloat16_rn(x);
}

// ------------- generic split-K SGEMM (W_map path) -------------
__global__ void __launch_bounds__(256) k_sgemm_atomic(
        const float* __restrict__ A, int lda,
        const float* __restrict__ B, int ldb,
        float* __restrict__ C, int M, int N, int kchunk) {
    __shared__ float As[8][64];
    __shared__ float Bs[8][64];
    const int k0b = blockIdx.z * kchunk;
    const int bm = blockIdx.y * 64, bn = blockIdx.x * 64;
    const int tid = threadIdx.x;
    const int lr = tid >> 2, lk = (tid & 3) * 2;
    const int tx = tid & 15, ty = tid >> 4;
    float acc[4][4];
#pragma unroll
    for (int i = 0; i < 4; i++)
#pragma unroll
        for (int j = 0; j < 4; j++) acc[i][j] = 0.f;

    const int kend = k0b + kchunk;
    for (int k0 = k0b; k0 < kend; k0 += 8) {
        float2 av = make_float2(0.f,0.f), bv = make_float2(0.f,0.f);
        int am = bm + lr, bn2 = bn + lr;
        if (am < M) av = *(const float2*)&A[(size_t)am*lda + k0 + lk];
        if (bn2 < N) bv = *(const float2*)&B[(size_t)bn2*ldb + k0 + lk];
        As[lk][lr] = av.x; As[lk+1][lr] = av.y;
        Bs[lk][lr] = bv.x; Bs[lk+1][lr] = bv.y;
        __syncthreads();
#pragma unroll
        for (int kk = 0; kk < 8; kk++) {
            float a[4], b[4];
            *(float4*)a = *(const float4*)&As[kk][ty*4];
            *(float4*)b = *(const float4*)&Bs[kk][tx*4];
#pragma unroll
            for (int i = 0; i < 4; i++)
#pragma unroll
                for (int j = 0; j < 4; j++) acc[i][j] += a[i]*b[j];
        }
        __syncthreads();
    }
#pragma unroll
    for (int i = 0; i < 4; i++) {
        int m = bm + ty*4 + i;
        if (m >= M) continue;
#pragma unroll
        for (int j = 0; j < 4; j++) {
            int n = bn + tx*4 + j;
            if (n < N) atomicAdd(&C[(size_t)m*N + n], acc[i][j]);
        }
    }
}

// ------------- tf32 MMA split-K GEMM (theta path) -------------
__global__ void __launch_bounds__(256, 2) k_gemm_tf32(
        const float* __restrict__ A, int lda, int M,
        const float* __restrict__ B, int ldb, int N,
        float* __restrict__ C, int ldc) {
    __shared__ float sA[128*TSTR];
    __shared__ float sB[128*TSTR];
    const int tid = threadIdx.x;
    const int bn = blockIdx.x * 128;
    const int kk0 = (int)blockIdx.z * TKC;

    const int w = tid >> 5;
    const int wm = w & 1;
    const int wn = w >> 1;
    const int lane = tid & 31;
    const int g = lane >> 2;
    const int t = lane & 3;

    float c[4][4][4];
#pragma unroll
    for (int mt = 0; mt < 4; mt++)
#pragma unroll
        for (int nt = 0; nt < 4; nt++)
#pragma unroll
            for (int q = 0; q < 4; q++) c[mt][nt][q] = 0.f;

    const int lrow = tid >> 2;
    const int lq   = (tid & 3) * 4;

    for (int it = 0; it < TKC/16; it++) {
        const int k0 = kk0 + it*16;
#pragma unroll
        for (int rep = 0; rep < 2; rep++) {
            int row = lrow + rep*64;
            float4 av = make_float4(0.f,0.f,0.f,0.f);
            float4 bv = make_float4(0.f,0.f,0.f,0.f);
            if (row < M)      av = *(const float4*)&A[(size_t)row*lda + k0 + lq];
            if (bn + row < N) {
                const float* bp = &B[(size_t)(bn + row)*ldb + k0 + lq];
                float2 u = *(const float2*)bp;
                float2 v2 = *(const float2*)(bp + 2);
                bv = make_float4(u.x, u.y, v2.x, v2.y);
            }
            *(float4*)&sA[row*TSTR + lq] = av;
            *(float4*)&sB[row*TSTR + lq] = bv;
        }
        __syncthreads();
#pragma unroll
        for (int ks = 0; ks < 16; ks += 8) {
            unsigned int af[4][4], bf[4][2];
#pragma unroll
            for (int mt = 0; mt < 4; mt++) {
                int base = (wm*64 + mt*16 + g)*TSTR + ks + t;
                af[mt][0] = f2tf32(sA[base]);
                af[mt][1] = f2tf32(sA[base + 8*TSTR]);
                af[mt][2] = f2tf32(sA[base + 4]);
                af[mt][3] = f2tf32(sA[base + 8*TSTR + 4]);
            }
#pragma unroll
            for (int nt = 0; nt < 4; nt++) {
                int base = (wn*32 + nt*8 + g)*TSTR + ks + t;
                bf[nt][0] = f2tf32(sB[base]);
                bf[nt][1] = f2tf32(sB[base + 4]);
            }
#pragma unroll
            for (int mt = 0; mt < 4; mt++)
#pragma unroll
                for (int nt = 0; nt < 4; nt++)
                    asm volatile(
                        "mma.sync.aligned.m16n8k8.row.col.f32.tf32.tf32.f32 "
                        "{%0,%1,%2,%3}, {%4,%5,%6,%7}, {%8,%9}, {%0,%1,%2,%3};"
                        : "+f"(c[mt][nt][0]), "+f"(c[mt][nt][1]),
                          "+f"(c[mt][nt][2]), "+f"(c[mt][nt][3])
                        : "r"(af[mt][0]), "r"(af[mt][1]), "r"(af[mt][2]), "r"(af[mt][3]),
                          "r"(bf[nt][0]), "r"(bf[nt][1]));
        }
        __syncthreads();
    }

#pragma unroll
    for (int mt = 0; mt < 4; mt++) {
        int m0 = wm*64 + mt*16 + g;
#pragma unroll
        for (int nt = 0; nt < 4; nt++) {
            int n0 = bn + wn*32 + nt*8 + 2*t;
            if (m0 < M) {
                if (n0   < N) atomicAdd(&C[(size_t)m0*ldc + n0],   c[mt][nt][0]);
                if (n0+1 < N) atomicAdd(&C[(size_t)m0*ldc + n0+1], c[mt][nt][1]);
            }
            if (m0 + 8 < M) {
                if (n0   < N) atomicAdd(&C[(size_t)(m0+8)*ldc + n0],   c[mt][nt][2]);
                if (n0+1 < N) atomicAdd(&C[(size_t)(m0+8)*ldc + n0+1], c[mt][nt][3]);
            }
        }
    }
}

// ------------- bf16 HMMA logits GEMM: 128x128 tile, exp->bf16 + rowsum -------------
__global__ void __launch_bounds__(256, 1) k_gemm_mma() {
    extern __shared__ unsigned int smw[];
    unsigned int* sA = smw;
    unsigned int* sB = smw + 128*SMS32;
    const int tid = threadIdx.x;
    const int bm = blockIdx.y * 128, bn = blockIdx.x * 128;

    {
        const uint4* gA = (const uint4*)(d_alphab + (size_t)bm*EP);
        const uint4* gB = (const uint4*)(d_wembb + (size_t)bn*EP);
        uint4* s4A = (uint4*)sA;
        uint4* s4B = (uint4*)sB;
        for (int i = tid; i < 128*38; i += 256) {
            int row = i / 38, c = i % 38;
            s4A[row*39 + c] = gA[row*38 + c];
            s4B[row*39 + c] = gB[row*38 + c];
        }
    }
    __syncthreads();

    const int w   = tid >> 5;
    const int wm  = w & 1;
    const int wn  = w >> 1;
    const int lane = tid & 31;
    const int g = lane >> 2;
    const int t = lane & 3;

    float c[4][4][4];
#pragma unroll
    for (int mt = 0; mt < 4; mt++)
#pragma unroll
        for (int nt = 0; nt < 4; nt++)
#pragma unroll
            for (int q = 0; q < 4; q++) c[mt][nt][q] = 0.f;

    const unsigned int* sAb = sA + (wm*64 + g)*SMS32 + t;
    const unsigned int* sBb = sB + (wn*32 + g)*SMS32 + t;

    for (int kk = 0; kk < EP/16; kk++) {
        const int ko = kk*8;
        unsigned int a[4][4], b[4][2];
#pragma unroll
        for (int mt = 0; mt < 4; mt++) {
            const unsigned int* p = sAb + mt*16*SMS32 + ko;
            a[mt][0] = p[0];
            a[mt][1] = p[8*SMS32];
            a[mt][2] = p[4];
            a[mt][3] = p[8*SMS32 + 4];
        }
#pragma unroll
        for (int nt = 0; nt < 4; nt++) {
            const unsigned int* p = sBb + nt*8*SMS32 + ko;
            b[nt][0] = p[0];
            b[nt][1] = p[4];
        }
#pragma unroll
        for (int mt = 0; mt < 4; mt++)
#pragma unroll
            for (int nt = 0; nt < 4; nt++)
                asm volatile(
                    "mma.sync.aligned.m16n8k16.row.col.f32.bf16.bf16.f32 "
                    "{%0,%1,%2,%3}, {%4,%5,%6,%7}, {%8,%9}, {%0,%1,%2,%3};"
                    : "+f"(c[mt][nt][0]), "+f"(c[mt][nt][1]),
                      "+f"(c[mt][nt][2]), "+f"(c[mt][nt][3])
                    : "r"(a[mt][0]), "r"(a[mt][1]), "r"(a[mt][2]), "r"(a[mt][3]),
                      "r"(b[nt][0]), "r"(b[nt][1]));
    }

#pragma unroll
    for (int mt = 0; mt < 4; mt++) {
        float rs0 = 0.f, rs1 = 0.f;
        int row0 = bm + wm*64 + mt*16 + g;
#pragma unroll
        for (int nt = 0; nt < 4; nt++) {
            int n = bn + wn*32 + nt*8 + t*2;
            float e0 = __expf(c[mt][nt][0]);
            float e1 = __expf(c[mt][nt][1]);
            float e2 = __expf(c[mt][nt][2]);
            float e3 = __expf(c[mt][nt][3]);
            if (n   >= VV) { e0 = 0.f; e2 = 0.f; }
            if (n+1 >= VV) { e1 = 0.f; e3 = 0.f; }
            rs0 += e0 + e1;
            rs1 += e2 + e3;
            *(__nv_bfloat162*)&d_elogh[(size_t)row0*VP + n] =
                __floats2bfloat162_rn(e0, e1);
            *(__nv_bfloat162*)&d_elogh[(size_t)(row0+8)*VP + n] =
                __floats2bfloat162_rn(e2, e3);
        }
        rs0 += __shfl_xor_sync(0xffffffffu, rs0, 1);
        rs0 += __shfl_xor_sync(0xffffffffu, rs0, 2);
        rs1 += __shfl_xor_sync(0xffffffffu, rs1, 1);
        rs1 += __shfl_xor_sync(0xffffffffu, rs1, 2);
        if (t == 0) {
            atomicAdd(&d_rowsum[row0],     rs0);
            atomicAdd(&d_rowsum[row0 + 8], rs1);
        }
    }
}

__global__ void k_addbias(const float* __restrict__ b_map) {
    int i = blockIdx.x * blockDim.x + threadIdx.x;
    if (i < TT*EHH) d_x[i] += b_map[i % EHH];
}

// ------------- LSTM input gates (parallel over t) -------------
__global__ void k_gin(const float* __restrict__ Wih, const float* __restrict__ bih,
                      const float* __restrict__ bhh, const float* __restrict__ x, int l) {
    int w = (blockIdx.x * blockDim.x + threadIdx.x) >> 5;
    int lane = threadIdx.x & 31;
    if (w >= TT*4*EHH) return;
    int t = w / (4*EHH), r = w % (4*EHH);
    const float* wr = Wih + (size_t)l*4*EHH*EHH + (size_t)r*EHH;
    const float* xr = x + t*EHH;
    float s = 0.f;
    for (int j = lane; j < EHH; j += 32) s += wr[j]*xr[j];
    s = warp_sum(s);
    if (lane == 0) d_gin[t*4*EHH + r] = s + bih[l*4*EHH + r] + bhh[l*4*EHH + r];
}

// ------------- LSTM recurrence: 8-CTA cluster, smem Whh, DSMEM h exchange -------------
__global__ void __launch_bounds__(256, 1) __cluster_dims__(NBLK, 1, 1)
k_lstm_cl(const float* __restrict__ Whh, float* __restrict__ yout, int l) {
    extern __shared__ float dynsm[];
    float* Wsm  = dynsm;                    // [LROWS][LSTR]
    float* hbuf = Wsm + LROWS*LSTR;         // [2][HSL] own slice (padded region)
    float* h_sm = hbuf + HBPAD;             // [EHH] gathered h (16B aligned)
    float* gacc = h_sm + EHH;               // [2][LROWS]
    float* gsum = gacc + 2*LROWS;           // [LROWS]
    const int tid = threadIdx.x;
    const int b = blockIdx.x;

    for (int idx = tid; idx < LROWS*EHH; idx += 256) {
        int row = idx / EHH, col = idx % EHH;
        int q = row / HSL, j = row % HSL;
        int grow = q*EHH + b*HSL + j;
        Wsm[row*LSTR + col] = Whh[(size_t)l*4*EHH*EHH + (size_t)grow*EHH + col];
    }
    if (tid < EHH) h_sm[tid] = 0.f;
    float c = 0.f;
    __syncthreads();

    const unsigned int hbuf_addr = smem_u32(hbuf);
    const int myrow = tid % LROWS;
    const int myhalf = tid / LROWS;
    const int src_cta = tid / HSL;
    const int src_j   = tid % HSL;

    for (int t = 0; t < TT; t++) {
        if (tid < 2*LROWS) {
            const float4* w4 = (const float4*)(Wsm + myrow*LSTR + myhalf*100);
            const float4* h4 = (const float4*)(h_sm + myhalf*100);
            float acc = 0.f;
#pragma unroll
            for (int jj = 0; jj < 25; jj++) {
                float4 wv = w4[jj], hv = h4[jj];
                acc += wv.x*hv.x + wv.y*hv.y + wv.z*hv.z + wv.w*hv.w;
            }
            gacc[myhalf*LROWS + myrow] = acc;
        }
        __syncthreads();
        if (tid < LROWS) {
            int q = tid / HSL, j = tid % HSL;
            gsum[tid] = gacc[tid] + gacc[LROWS + tid]
                      + d_gin[t*4*EHH + q*EHH + b*HSL + j];
        }
        __syncthreads();
        if (tid < HSL) {
            float ig = sigmf(gsum[tid]);
            float fg = sigmf(gsum[HSL + tid]);
            float gg = tanhf(gsum[2*HSL + tid]);
            float og = sigmf(gsum[3*HSL + tid]);
            c = fg*c + ig*gg;
            float h = og*tanhf(c);
            hbuf[((t + 1) & 1)*HSL + tid] = h;
            yout[t*EHH + b*HSL + tid] = h;
        }
        CLUSTER_SYNC_();
        if (t < TT - 1) {
            if (tid < EHH) {
                unsigned int pa = mapa_smem(
                    hbuf_addr + (((t + 1) & 1)*HSL + src_j)*4u, (unsigned int)src_cta);
                h_sm[tid] = ld_dsmem(pa);
            }
            __syncthreads();
        }
    }
    CLUSTER_SYNC_();
}

// ------------- eta: parallel input part (over all t) -------------
// d_etain[t][o] = W[o][0:200] . y[t] + bias[o]   (o<50: mu weights, o>=50: ls)
__global__ void k_etain(const float* __restrict__ Wmu, const float* __restrict__ bmu,
                        const float* __restrict__ Wls, const float* __restrict__ bls) {
    int w = (blockIdx.x * blockDim.x + threadIdx.x) >> 5;
    int lane = threadIdx.x & 31;
    if (w >= TT*2*KTOP) return;
    int t = w / (2*KTOP), o = w % (2*KTOP);
    const float* W = (o < KTOP) ? (Wmu + o*(EHH+KTOP)) : (Wls + (o-KTOP)*(EHH+KTOP));
    const float* yr = d_y + t*EHH;
    float s = 0.f;
    for (int j = lane; j < EHH; j += 32) s += W[j]*yr[j];
    s = warp_sum(s);
    if (lane == 0)
        d_etain[t*2*KTOP + o] = s + ((o < KTOP) ? bmu[o] : bls[o-KTOP]);
}

// ------------- eta: tiny sequential recurrence (50x50 in smem) + KL -------------
__global__ void k_eta_rec(const float* __restrict__ Wmu, const float* __restrict__ Wls) {
    __shared__ float Bm[2*KTOP*KTOP];       // rows 0-49: Bmu, 50-99: Bls
    __shared__ float eta_s[KTOP], mu_s[KTOP], ls_s[KTOP];
    int tid = threadIdx.x;                  // 128 threads
    for (int i = tid; i < KTOP*KTOP; i += 128) {
        int o = i / KTOP, j = i % KTOP;
        Bm[i]             = Wmu[o*(EHH+KTOP) + EHH + j];
        Bm[KTOP*KTOP + i] = Wls[o*(EHH+KTOP) + EHH + j];
    }
    __syncthreads();

    float kl_acc = 0.f;
    for (int t = 0; t < TT; t++) {
        if (tid < 2*KTOP) {
            float s = d_etain[t*2*KTOP + tid];
            if (t > 0) {
                const float* Br = Bm + tid*KTOP;
                float a0 = 0.f, a1 = 0.f, a2 = 0.f, a3 = 0.f;
#pragma unroll
                for (int j = 0; j < 48; j += 4) {
                    a0 += Br[j]   * eta_s[j];
                    a1 += Br[j+1] * eta_s[j+1];
                    a2 += Br[j+2] * eta_s[j+2];
                    a3 += Br[j+3] * eta_s[j+3];
                }
                a0 += Br[48]*eta_s[48];
                a1 += Br[49]*eta_s[49];
                s += (a0 + a1) + (a2 + a3);
            }
            if (tid < KTOP) mu_s[tid] = s;
            else            ls_s[tid - KTOP] = s;
        }
        __syncthreads();
        if (tid < KTOP) {
            float mu = mu_s[tid], ls = ls_s[tid];
            float term;
            if (t == 0) term = 0.5f*((__expf(ls) + mu*mu)/(1.f+EPSF) - 1.f - ls);
            else {
                float dd = mu - eta_s[tid];
                term = 0.5f*((__expf(ls) + dd*dd)/(DELTAF+EPSF) - 1.f + LOGDF - ls);
            }
            kl_acc += term;
            d_eta[t*KTOP + tid] = mu;
        }
        __syncthreads();
        if (tid < KTOP) eta_s[tid] = mu_s[tid];
        __syncthreads();
    }
    block_add_double(kl_acc, 2);
}

// ------------- theta hidden epilogue -------------
__global__ void k_theta_h(const float* __restrict__ b_theta, const float* __restrict__ W_theta,
                          const int* __restrict__ times) {
    int idx = blockIdx.x * blockDim.x + threadIdx.x;
    if (idx >= BB*THH) return;
    int b = idx / THH, i = idx % THH;
    int tb = times[b];
    float v = d_hth[idx] + b_theta[i];
    const float* wrow = W_theta + (size_t)i*(VV+KTOP) + VV;
    const float* er = d_eta + tb*KTOP;
#pragma unroll 10
    for (int k = 0; k < KTOP; k++) v += er[k]*wrow[k];
    d_hth[idx] = tanhf(v);
}

// ------------- mu_t / ls_t -------------
__global__ void k_theta_muls(const float* __restrict__ Wmu, const float* __restrict__ bmu,
                             const float* __restrict__ Wls, const float* __restrict__ bls) {
    int w = (blockIdx.x * blockDim.x + threadIdx.x) >> 5;
    int lane = threadIdx.x & 31;
    if (w >= BB*2*KTOP) return;
    int b = w / (2*KTOP), q = w % (2*KTOP);
    int kk = q % KTOP;
    bool isls = q >= KTOP;
    const float* W = (isls ? Wls : Wmu) + kk*THH;
    const float* h = d_hth + b*THH;
    float s = 0.f;
    for (int j = lane; j < THH; j += 32) s += W[j]*h[j];
    s = warp_sum(s);
    if (lane == 0) {
        s += (isls ? bls : bmu)[kk];
        (isls ? d_ls_t : d_mu_t)[b*KTOP + kk] = s;
    }
}

// ------------- theta softmax + kl_theta -------------
__global__ void k_theta_softkl(const int* __restrict__ times) {
    __shared__ float mus[KTOP], es[KTOP], red2[2];
    int b = blockIdx.x, tid = threadIdx.x;
    if (tid < KTOP) mus[tid] = d_mu_t[b*KTOP + tid];
    __syncthreads();
    if (tid == 0) {
        float m = -1e30f;
        for (int k = 0; k < KTOP; k++) m = fmaxf(m, mus[k]);
        red2[0] = m;
    }
    __syncthreads();
    if (tid < KTOP) es[tid] = __expf(mus[tid] - red2[0]);
    __syncthreads();
    if (tid == 0) {
        float s = 0.f;
        for (int k = 0; k < KTOP; k++) s += es[k];
        red2[1] = 1.f/s;
    }
    __syncthreads();
    float kl = 0.f;
    if (tid < KTOP) {
        d_theta[b*KTOP + tid] = es[tid]*red2[1];
        float ls = d_ls_t[b*KTOP + tid];
        float e  = d_eta[times[b]*KTOP + tid];
        float dmu = mus[tid] - e;
        kl = 0.5f*((__expf(ls) + dmu*dmu)/(1.f+EPSF) - 1.f - ls);
    }
    block_add_double(kl, 3);
}

// ------------- kl_alpha (grid-stride, few blocks -> few atomics) -------------
__global__ void k_klalpha(const float* __restrict__ mq, const float* __restrict__ lsq) {
    float term = 0.f;
    for (int idx = blockIdx.x * blockDim.x + threadIdx.x;
         idx < KTOP*TT*EE; idx += gridDim.x * blockDim.x) {
        int t = (idx / EE) % TT;
        float mu = mq[idx], ls = lsq[idx];
        if (t == 0) term += 0.5f*((__expf(ls) + mu*mu)/(1.f+EPSF) - 1.f - ls);
        else {
            float d = mu - mq[idx - EE];
            term += 0.5f*((__expf(ls) + d*d)/(DELTAF+EPSF) - 1.f + LOGDF - ls);
        }
    }
    block_add_double(term, 1);
}

// ------------- nll: grid (B, NVCH), inner v loop -> 400 atomics total -------------
__global__ void k_nll(const float* __restrict__ bows, const int* __restrict__ times) {
    __shared__ float wsh[KTOP];
    int b = blockIdx.x;
    int t = times[b];
    int tid = threadIdx.x;
    if (tid < KTOP) {
        int row = t*KTOP + tid;
        wsh[tid] = d_theta[b*KTOP + tid] / d_rowsum[row];
    }
    __syncthreads();
    int v0 = blockIdx.y * VCH;
    int v1 = v0 + VCH; if (v1 > VV) v1 = VV;
    float val = 0.f;
    for (int v = v0 + tid; v < v1; v += 256) {
        const __nv_bfloat16* base = d_elogh + (size_t)(t*KTOP)*VP + v;
        float p = 0.f;
#pragma unroll 10
        for (int k = 0; k < KTOP; k++)
            p += wsh[k] * __bfloat162float(base[(size_t)k*VP]);
        val += __logf(p + EPSF) * bows[(size_t)b*VV + v];
    }
    block_add_double(val, 0);
}

// ------------- finalize -------------
__global__ void k_finalize(float* out, int n) {
    if (threadIdx.x == 0) {
        float nll = -(float)d_scald[0];
        float ka = (float)d_scald[1];
        float ke = (float)d_scald[2];
        float kt = (float)d_scald[3];
        float vals[5] = {nll + ka + ke + kt, nll, ka, ke, kt};
        for (int i = 0; i < n; i++) out[i] = (i < 5) ? vals[i] : 0.f;
    }
}

extern "C" void kernel_launch(void* const* d_in, const int* in_sizes, int n_in,
                              void* d_out, int out_size) {
    const float* bows      = (const float*)d_in[0];
    const float* nbows     = (const float*)d_in[1];
    const float* rnn_inp   = (const float*)d_in[2];
    const float* word_emb  = (const float*)d_in[3];
    const float* mu_q_a    = (const float*)d_in[4];
    const float* ls_q_a    = (const float*)d_in[5];
    const float* W_theta   = (const float*)d_in[6];
    const float* b_theta   = (const float*)d_in[7];
    const float* W_mu_th   = (const float*)d_in[8];
    const float* b_mu_th   = (const float*)d_in[9];
    const float* W_ls_th   = (const float*)d_in[10];
    const float* b_ls_th   = (const float*)d_in[11];
    const float* W_map     = (const float*)d_in[12];
    const float* b_map     = (const float*)d_in[13];
    const float* lstm_Wih  = (const float*)d_in[14];
    const float* lstm_Whh  = (const float*)d_in[15];
    const float* lstm_bih  = (const float*)d_in[16];
    const float* lstm_bhh  = (const float*)d_in[17];
    const float* W_mu_eta  = (const float*)d_in[18];
    const float* b_mu_eta  = (const float*)d_in[19];
    const float* W_ls_eta  = (const float*)d_in[20];
    const float* b_ls_eta  = (const float*)d_in[21];
    const int*   times     = (const int*)d_in[22];
    float* out = (float*)d_out;

    float *dx, *dy, *dhth;
    cudaGetSymbolAddress((void**)&dx, d_x);
    cudaGetSymbolAddress((void**)&dy, d_y);
    cudaGetSymbolAddress((void**)&dhth, d_hth);

    const int mma_smem  = 2 * 128 * SMS32 * 4;
    const int lstm_smem = (LROWS*LSTR + HBPAD + EHH + 2*LROWS + LROWS) * 4;

    static cudaStream_t s2 = nullptr;
    static cudaEvent_t evA = nullptr, evB = nullptr;
    if (s2 == nullptr) {
        cudaFuncSetAttribute(k_gemm_mma,
            cudaFuncAttributeMaxDynamicSharedMemorySize, mma_smem);
        cudaFuncSetAttribute(k_lstm_cl,
            cudaFuncAttributeMaxDynamicSharedMemorySize, lstm_smem);
        cudaStreamCreateWithFlags(&s2, cudaStreamNonBlocking);
        cudaEventCreateWithFlags(&evA, cudaEventDisableTiming);
        cudaEventCreateWithFlags(&evB, cudaEventDisableTiming);
    }

    // -------- stream 0: zero, then fork --------
    k_zero<<<(BB*THH + 255)/256, 256>>>();
    cudaEventRecord(evA, 0);
    cudaStreamWaitEvent(s2, evA, 0);

    // -------- side stream: chip-wide independent work --------
    k_alphaT<<<(MP*EP + 255)/256, 256, 0, s2>>>(mu_q_a);
    k_wembpad<<<(int)(((size_t)VP*EP + 255)/256), 256, 0, s2>>>(word_emb);
    {
        dim3 g((THH + 127)/128, 1, TZ);
        k_gemm_tf32<<<g, 256, 0, s2>>>(nbows, VV, BB, W_theta, VV + KTOP, THH,
                                       dhth, THH);
    }
    k_klalpha<<<232, 256, 0, s2>>>(mu_q_a, ls_q_a);
    {
        dim3 g(VP/128, MP/128);
        k_gemm_mma<<<g, 256, mma_smem, s2>>>();
    }
    cudaEventRecord(evB, s2);

    // -------- stream 0: serial LSTM/eta chain (overlapped with s2) --------
    {
        dim3 g((EHH + 63)/64, (TT + 63)/64, 25);
        k_sgemm_atomic<<<g, 256>>>(rnn_inp, VV, W_map, VV, dx, TT, EHH, 1200);
    }
    k_addbias<<<(TT*EHH + 255)/256, 256>>>(b_map);

    float* lin = dx; float* lout = dy;
    for (int l = 0; l < LL; l++) {
        k_gin<<<(TT*4*EHH*32 + 255)/256, 256>>>(lstm_Wih, lstm_bih, lstm_bhh, lin, l);
        k_lstm_cl<<<NBLK, 256, lstm_smem>>>(lstm_Whh, lout, l);
        float* tmp = lin; lin = lout; lout = tmp;
    }

    k_etain<<<500, 256>>>(W_mu_eta, b_mu_eta, W_ls_eta, b_ls_eta);
    k_eta_rec<<<1, 128>>>(W_mu_eta, W_ls_eta);

    // -------- join --------
    cudaStreamWaitEvent(0, evB, 0);

    k_theta_h<<<(BB*THH + 255)/256, 256>>>(b_theta, W_theta, times);
    k_theta_muls<<<(BB*2*KTOP*32 + 255)/256, 256>>>(W_mu_th, b_mu_th, W_ls_th, b_ls_th);
    k_theta_softkl<<<BB, 64>>>(times);

    {
        dim3 g(BB, NVCH);
        k_nll<<<g, 256>>>(bows, times);
    }

    k_finalize<<<1, 32>>>(out, out_size);
}